// round 1
// baseline (speedup 1.0000x reference)
#include <cuda_runtime.h>
#include <math.h>

#define N_PTS 524288

// ---------------- scratch (device globals; no allocation) ----------------
__device__ float4 d_g0t[32 * 32 * 32];
__device__ float4 d_g1t[64 * 64 * 64];
__device__ float4 d_g2t[128 * 128 * 128];
__device__ float4 d_g3t[256 * 256 * 256];
__device__ float4 d_coeft[64 * 64 * 64];
__device__ float  d_feats[16 * N_PTS];   // transposed: feats[k][pt]

// ---------------- channels-last transpose: [4,V] -> [V] float4 ----------------
__global__ void transpose_cl(const float* __restrict__ src, float4* __restrict__ dst, int V) {
    int v = blockIdx.x * blockDim.x + threadIdx.x;
    if (v < V) {
        dst[v] = make_float4(src[v], src[v + V], src[v + 2 * V], src[v + 3 * V]);
    }
}

// ---------------- trilerp on channels-last grid ----------------
__device__ __forceinline__ float4 trilerp4(const float4* __restrict__ g, int R,
                                           float px, float py, float pz) {
    float s = 0.5f * (float)(R - 1);
    float cx = (px + 1.0f) * s;
    float cy = (py + 1.0f) * s;
    float cz = (pz + 1.0f) * s;
    float fx0 = floorf(cx), fy0 = floorf(cy), fz0 = floorf(cz);
    float fx = cx - fx0, fy = cy - fy0, fz = cz - fz0;
    int x0 = min(max((int)fx0, 0), R - 1);
    int y0 = min(max((int)fy0, 0), R - 1);
    int z0 = min(max((int)fz0, 0), R - 1);
    int x1 = min(x0 + 1, R - 1);
    int y1 = min(y0 + 1, R - 1);
    int z1 = min(z0 + 1, R - 1);

    const float4 v000 = __ldg(&g[(z0 * R + y0) * R + x0]);
    const float4 v001 = __ldg(&g[(z0 * R + y0) * R + x1]);
    const float4 v010 = __ldg(&g[(z0 * R + y1) * R + x0]);
    const float4 v011 = __ldg(&g[(z0 * R + y1) * R + x1]);
    const float4 v100 = __ldg(&g[(z1 * R + y0) * R + x0]);
    const float4 v101 = __ldg(&g[(z1 * R + y0) * R + x1]);
    const float4 v110 = __ldg(&g[(z1 * R + y1) * R + x0]);
    const float4 v111 = __ldg(&g[(z1 * R + y1) * R + x1]);

    float gx = 1.0f - fx, gy = 1.0f - fy, gz = 1.0f - fz;
    float w00 = gz * gy, w01 = gz * fy, w10 = fz * gy, w11 = fz * fy;

    float4 r;
    r.x = (v000.x * gx + v001.x * fx) * w00 + (v010.x * gx + v011.x * fx) * w01
        + (v100.x * gx + v101.x * fx) * w10 + (v110.x * gx + v111.x * fx) * w11;
    r.y = (v000.y * gx + v001.y * fx) * w00 + (v010.y * gx + v011.y * fx) * w01
        + (v100.y * gx + v101.y * fx) * w10 + (v110.y * gx + v111.y * fx) * w11;
    r.z = (v000.z * gx + v001.z * fx) * w00 + (v010.z * gx + v011.z * fx) * w01
        + (v100.z * gx + v101.z * fx) * w10 + (v110.z * gx + v111.z * fx) * w11;
    r.w = (v000.w * gx + v001.w * fx) * w00 + (v010.w * gx + v011.w * fx) * w01
        + (v100.w * gx + v101.w * fx) * w10 + (v110.w * gx + v111.w * fx) * w11;
    return r;
}

__device__ __forceinline__ float fracf(float a) { return a - floorf(a); }

// ---------------- encode: grids -> 16 features per point ----------------
__global__ void encode_kernel(const float* __restrict__ x) {
    int i = blockIdx.x * blockDim.x + threadIdx.x;
    if (i >= N_PTS) return;
    float px = x[3 * i + 0];
    float py = x[3 * i + 1];
    float pz = x[3 * i + 2];

    float4 coef = trilerp4(d_coeft, 64, px, py, pz);

    // grid 0: F=1, R=32, scale coef.x
    {
        float ex = 2.0f * fracf(px * 1.0f) - 1.0f;
        float ey = 2.0f * fracf(py * 1.0f) - 1.0f;
        float ez = 2.0f * fracf(pz * 1.0f) - 1.0f;
        float4 v = trilerp4(d_g0t, 32, ex, ey, ez);
        d_feats[0 * N_PTS + i] = v.x * coef.x;
        d_feats[1 * N_PTS + i] = v.y * coef.x;
        d_feats[2 * N_PTS + i] = v.z * coef.x;
        d_feats[3 * N_PTS + i] = v.w * coef.x;
    }
    // grid 1: F=2, R=64, scale coef.y
    {
        float ex = 2.0f * fracf(px * 2.0f) - 1.0f;
        float ey = 2.0f * fracf(py * 2.0f) - 1.0f;
        float ez = 2.0f * fracf(pz * 2.0f) - 1.0f;
        float4 v = trilerp4(d_g1t, 64, ex, ey, ez);
        d_feats[4 * N_PTS + i] = v.x * coef.y;
        d_feats[5 * N_PTS + i] = v.y * coef.y;
        d_feats[6 * N_PTS + i] = v.z * coef.y;
        d_feats[7 * N_PTS + i] = v.w * coef.y;
    }
    // grid 2: F=4, R=128, scale coef.z
    {
        float ex = 2.0f * fracf(px * 4.0f) - 1.0f;
        float ey = 2.0f * fracf(py * 4.0f) - 1.0f;
        float ez = 2.0f * fracf(pz * 4.0f) - 1.0f;
        float4 v = trilerp4(d_g2t, 128, ex, ey, ez);
        d_feats[8 * N_PTS + i]  = v.x * coef.z;
        d_feats[9 * N_PTS + i]  = v.y * coef.z;
        d_feats[10 * N_PTS + i] = v.z * coef.z;
        d_feats[11 * N_PTS + i] = v.w * coef.z;
    }
    // grid 3: F=8, R=256, scale coef.w
    {
        float ex = 2.0f * fracf(px * 8.0f) - 1.0f;
        float ey = 2.0f * fracf(py * 8.0f) - 1.0f;
        float ez = 2.0f * fracf(pz * 8.0f) - 1.0f;
        float4 v = trilerp4(d_g3t, 256, ex, ey, ez);
        d_feats[12 * N_PTS + i] = v.x * coef.w;
        d_feats[13 * N_PTS + i] = v.y * coef.w;
        d_feats[14 * N_PTS + i] = v.z * coef.w;
        d_feats[15 * N_PTS + i] = v.w * coef.w;
    }
}

// ---------------- MLP ----------------
// Block: 256 threads. Tile: 256 points x 128 outputs.
// smem: hbuf[k][pt] = [128][256] f32 (128KB), wsm[k][j] = [128][128] f32 (64KB).
// Thread (ptg = tid&31, og = tid>>5): 8 points x 16 outputs register tile.
struct MLPW {
    const float* W[7];
    const float* B[7];
};

__global__ void __launch_bounds__(256, 1) mlp_kernel(MLPW p, float* __restrict__ out) {
    extern __shared__ float sm[];
    float* hbuf = sm;                 // 128*256 floats
    float* wsm  = sm + 128 * 256;     // 128*128 floats

    const int tid  = threadIdx.x;
    const int base = blockIdx.x * 256;
    const int ptg  = tid & 31;
    const int og   = tid >> 5;
    const int pts  = ptg * 8;
    const int outs = og * 16;

    // stage layer-0 input (16 rows x 256 pts), coalesced
#pragma unroll
    for (int r = 0; r < 16; r++) {
        hbuf[r * 256 + tid] = d_feats[r * N_PTS + base + tid];
    }

    for (int l = 0; l < 7; l++) {
        const int K = (l == 0) ? 16 : 128;

        // stage W[l] into smem (K*128 floats), float4 coalesced
        const float4* wg = (const float4*)p.W[l];
        float4* wsd = (float4*)wsm;
        const int nw4 = (K * 128) / 4;
        for (int idx = tid; idx < nw4; idx += 256) wsd[idx] = __ldg(&wg[idx]);
        __syncthreads();

        float bv[16];
#pragma unroll
        for (int oi = 0; oi < 16; oi++) bv[oi] = __ldg(&p.B[l][outs + oi]);

        float acc[8][16];
#pragma unroll
        for (int pi = 0; pi < 8; pi++)
#pragma unroll
            for (int oi = 0; oi < 16; oi++) acc[pi][oi] = 0.0f;

#pragma unroll 4
        for (int k = 0; k < K; k++) {
            const float4 h0 = *(const float4*)(hbuf + k * 256 + pts);
            const float4 h1 = *(const float4*)(hbuf + k * 256 + pts + 4);
            const float4* wr = (const float4*)(wsm + k * 128 + outs);
            const float4 w0 = wr[0], w1 = wr[1], w2 = wr[2], w3 = wr[3];
            const float hv[8] = {h0.x, h0.y, h0.z, h0.w, h1.x, h1.y, h1.z, h1.w};
            const float wv[16] = {w0.x, w0.y, w0.z, w0.w, w1.x, w1.y, w1.z, w1.w,
                                  w2.x, w2.y, w2.z, w2.w, w3.x, w3.y, w3.z, w3.w};
#pragma unroll
            for (int pi = 0; pi < 8; pi++)
#pragma unroll
                for (int oi = 0; oi < 16; oi++)
                    acc[pi][oi] = fmaf(hv[pi], wv[oi], acc[pi][oi]);
        }
        __syncthreads();

        if (l < 6) {
            // relu(acc + b) -> hbuf[j][pt] for next layer
#pragma unroll
            for (int oi = 0; oi < 16; oi++) {
                const int j = outs + oi;
                float4 a, b;
                a.x = fmaxf(acc[0][oi] + bv[oi], 0.0f);
                a.y = fmaxf(acc[1][oi] + bv[oi], 0.0f);
                a.z = fmaxf(acc[2][oi] + bv[oi], 0.0f);
                a.w = fmaxf(acc[3][oi] + bv[oi], 0.0f);
                b.x = fmaxf(acc[4][oi] + bv[oi], 0.0f);
                b.y = fmaxf(acc[5][oi] + bv[oi], 0.0f);
                b.z = fmaxf(acc[6][oi] + bv[oi], 0.0f);
                b.w = fmaxf(acc[7][oi] + bv[oi], 0.0f);
                *(float4*)(hbuf + j * 256 + pts)     = a;
                *(float4*)(hbuf + j * 256 + pts + 4) = b;
            }
            // next layer's W staging + pre-acc barrier provide ordering
        } else {
            // final layer: acc + b -> global out [N,128]
#pragma unroll
            for (int pi = 0; pi < 8; pi++) {
                float* orow = out + (size_t)(base + pts + pi) * 128 + outs;
#pragma unroll
                for (int oq = 0; oq < 4; oq++) {
                    float4 o;
                    o.x = acc[pi][oq * 4 + 0] + bv[oq * 4 + 0];
                    o.y = acc[pi][oq * 4 + 1] + bv[oq * 4 + 1];
                    o.z = acc[pi][oq * 4 + 2] + bv[oq * 4 + 2];
                    o.w = acc[pi][oq * 4 + 3] + bv[oq * 4 + 3];
                    *(float4*)(orow + oq * 4) = o;
                }
            }
        }
    }
}

// ---------------- launch ----------------
extern "C" void kernel_launch(void* const* d_in, const int* in_sizes, int n_in,
                              void* d_out, int out_size) {
    const float* x    = (const float*)d_in[0];
    const float* g0   = (const float*)d_in[1];
    const float* g1   = (const float*)d_in[2];
    const float* g2   = (const float*)d_in[3];
    const float* g3   = (const float*)d_in[4];
    const float* coef = (const float*)d_in[5];

    MLPW p;
    for (int j = 0; j < 7; j++) {
        p.W[j] = (const float*)d_in[6 + 2 * j];
        p.B[j] = (const float*)d_in[7 + 2 * j];
    }
    float* out = (float*)d_out;

    cudaFuncSetAttribute(mlp_kernel, cudaFuncAttributeMaxDynamicSharedMemorySize,
                         (128 * 256 + 128 * 128) * 4);

    void* ptr;
    cudaGetSymbolAddress(&ptr, d_g0t);   float4* g0t = (float4*)ptr;
    cudaGetSymbolAddress(&ptr, d_g1t);   float4* g1t = (float4*)ptr;
    cudaGetSymbolAddress(&ptr, d_g2t);   float4* g2t = (float4*)ptr;
    cudaGetSymbolAddress(&ptr, d_g3t);   float4* g3t = (float4*)ptr;
    cudaGetSymbolAddress(&ptr, d_coeft); float4* ct  = (float4*)ptr;

    transpose_cl<<<(32 * 32 * 32 + 255) / 256, 256>>>(g0, g0t, 32 * 32 * 32);
    transpose_cl<<<(64 * 64 * 64 + 255) / 256, 256>>>(g1, g1t, 64 * 64 * 64);
    transpose_cl<<<(128 * 128 * 128 + 255) / 256, 256>>>(g2, g2t, 128 * 128 * 128);
    transpose_cl<<<(256 * 256 * 256 + 255) / 256, 256>>>(g3, g3t, 256 * 256 * 256);
    transpose_cl<<<(64 * 64 * 64 + 255) / 256, 256>>>(coef, ct, 64 * 64 * 64);

    encode_kernel<<<N_PTS / 256, 256>>>(x);

    mlp_kernel<<<N_PTS / 256, 256, (128 * 256 + 128 * 128) * 4>>>(p, out);
}